// round 16
// baseline (speedup 1.0000x reference)
#include <cuda_runtime.h>
#include <cuda_fp16.h>
#include <cstdint>

#define NTOK 4096
#define DM   512
#define DPE  16
#define NH   8
#define HD   64
#define LOG2E   1.4426950408889634f
#define SCALE2  0.18033688011112042f   // 0.125 * log2(e)
#define SOFT_OFF 4.0f                  // static softmax offset (cancels exactly)

// Scratch (no allocations allowed)
__device__ __half g_xh[NTOK * DM];        // x pre-converted to fp16
__device__ __half g_wqkvh[DM * 3 * DM];   // w_qkv fp16
__device__ __half g_wouth[DM * DM];       // w_out fp16
__device__ __half g_Q[NH * NTOK * HD];    // [h][n][d]
__device__ __half g_K[NH * NTOK * HD];
__device__ __half g_V[NH * NTOK * HD];
__device__ float  g_peb[NH * NTOK];       // [h][n] (bias - offset) * log2(e)
__device__ __half g_AO[NTOK * DM];        // attention output fp16, [n][h*64+d]

// ---------------------------------------------------------------------------
__device__ __forceinline__ void mma_f16(float d[4], const uint32_t a[4],
                                        const uint32_t b[2]) {
    asm("mma.sync.aligned.m16n8k16.row.col.f32.f16.f16.f32 "
        "{%0,%1,%2,%3}, {%4,%5,%6,%7}, {%8,%9}, {%0,%1,%2,%3};"
        : "+f"(d[0]), "+f"(d[1]), "+f"(d[2]), "+f"(d[3])
        : "r"(a[0]), "r"(a[1]), "r"(a[2]), "r"(a[3]), "r"(b[0]), "r"(b[1]));
}

__device__ __forceinline__ uint32_t pack2(float lo, float hi) {
    __half2 h = __floats2half2_rn(lo, hi);
    return *reinterpret_cast<uint32_t*>(&h);
}

__device__ __forceinline__ uint32_t ex2_h2(uint32_t x) {
    uint32_t r;
    asm("ex2.approx.f16x2 %0, %1;" : "=r"(r) : "r"(x));
    return r;
}

// ---------------------------------------------------------------------------
// One-shot fp32 -> fp16 conversion of x, w_qkv, w_out (4 floats per thread).
// ---------------------------------------------------------------------------
#define CVT_NX (NTOK * DM / 4)
#define CVT_NQ (DM * 3 * DM / 4)
#define CVT_NO (DM * DM / 4)
__global__ void cvt_inputs(const float* __restrict__ x,
                           const float* __restrict__ wqkv,
                           const float* __restrict__ wout) {
    const int s = blockIdx.x * 256 + threadIdx.x;
    const float4* src;
    __half* dst;
    int off;
    if (s < CVT_NX)                { src = (const float4*)x;    dst = g_xh;    off = s; }
    else if (s < CVT_NX + CVT_NQ)  { src = (const float4*)wqkv; dst = g_wqkvh; off = s - CVT_NX; }
    else                           { src = (const float4*)wout; dst = g_wouth; off = s - CVT_NX - CVT_NQ; }
    float4 v = src[off];
    uint2 p;
    p.x = pack2(v.x, v.y);
    p.y = pack2(v.z, v.w);
    *(uint2*)&dst[(size_t)off * 4] = p;
}

// ---------------------------------------------------------------------------
// fp16-in fp16-compute GEMM: C[M x NCOLS] = A[M x 512] * B[512 x NCOLS] + bias
// Block tile 128x128, 8 warps (2m x 4n), warp tile 64x32, BK=32.
// A/B selected from device globals by QKV_SCATTER (QKV: A=g_xh,B=g_wqkvh;
// out-proj: A=g_AO,B=g_wouth). All inputs pre-converted fp16: LDG traffic
// halved, no cvt in staging, prefetch regs 48->16 => 2 CTAs/SM.
// As [row][k] stride 40 halves (20 words: 20g+t distinct mod 32);
// Bp [kp][col] half2 stride 136 words (8t+g distinct mod 32).
// ---------------------------------------------------------------------------
template <int NCOLS, bool QKV_SCATTER>
__global__ __launch_bounds__(256, 2) void gemm_mma(const float* __restrict__ bias,
                                                   float* __restrict__ C) {
    __shared__ __half   As[128 * 40];    // 10240 B
    __shared__ uint32_t Bp[16 * 136];    //  8704 B

    const __half* A = QKV_SCATTER ? g_xh : g_AO;
    const __half* B = QKV_SCATTER ? g_wqkvh : g_wouth;

    const int row0 = blockIdx.x * 128;
    const int col0 = blockIdx.y * 128;
    const int tid  = threadIdx.x;
    const int warp = tid >> 5;
    const int lane = tid & 31;
    const int g    = lane >> 2;
    const int t    = lane & 3;
    const int wm   = (warp >> 2) * 64;
    const int wn   = (warp & 3) * 32;

    const uint32_t* Asw = (const uint32_t*)As;

    // staging indices: A 2 tasks/thread, B 1 task/thread
    const int bkp = tid >> 4;            // 0..15 (k-pair)
    const int bc8 = (tid & 15) << 3;     // 0..120 (col group of 8)

    uint4 apre[2], bpa, bpb;

    // ---- prologue LDG (tile 0) ----
#pragma unroll
    for (int ii = 0; ii < 2; ii++) {
        const int id = tid + ii * 256;
        apre[ii] = *(const uint4*)&A[(size_t)(row0 + (id >> 2)) * DM + ((id & 3) << 3)];
    }
    bpa = *(const uint4*)&B[(size_t)(2 * bkp) * NCOLS + col0 + bc8];
    bpb = *(const uint4*)&B[(size_t)(2 * bkp + 1) * NCOLS + col0 + bc8];

    float acc[4][4][4];
#pragma unroll
    for (int mt = 0; mt < 4; mt++)
#pragma unroll
        for (int nt = 0; nt < 4; nt++)
#pragma unroll
            for (int c = 0; c < 4; c++) acc[mt][nt][c] = 0.f;

    for (int it = 0; it < 16; it++) {
        // ---- STS staged tile ----
#pragma unroll
        for (int ii = 0; ii < 2; ii++) {
            const int id = tid + ii * 256;
            *(uint4*)&As[(id >> 2) * 40 + ((id & 3) << 3)] = apre[ii];
        }
        {
            const uint32_t* ea = (const uint32_t*)&bpa;
            const uint32_t* eb = (const uint32_t*)&bpb;
            uint32_t w[8];
#pragma unroll
            for (int j = 0; j < 4; j++) {
                w[2 * j]     = __byte_perm(ea[j], eb[j], 0x5410);
                w[2 * j + 1] = __byte_perm(ea[j], eb[j], 0x7632);
            }
            *(uint4*)&Bp[bkp * 136 + bc8]     = *(uint4*)&w[0];
            *(uint4*)&Bp[bkp * 136 + bc8 + 4] = *(uint4*)&w[4];
        }
        __syncthreads();

        // ---- prefetch LDG for next tile ----
        if (it < 15) {
            const int kn = (it + 1) * 32;
#pragma unroll
            for (int ii = 0; ii < 2; ii++) {
                const int id = tid + ii * 256;
                apre[ii] = *(const uint4*)&A[(size_t)(row0 + (id >> 2)) * DM + kn + ((id & 3) << 3)];
            }
            bpa = *(const uint4*)&B[(size_t)(kn + 2 * bkp) * NCOLS + col0 + bc8];
            bpb = *(const uint4*)&B[(size_t)(kn + 2 * bkp + 1) * NCOLS + col0 + bc8];
        }

        // ---- compute: 2 k16 steps x 16 mma ----
#pragma unroll
        for (int ks = 0; ks < 2; ks++) {
            uint32_t af[4][4];
#pragma unroll
            for (int mt = 0; mt < 4; mt++) {
                const int r = wm + mt * 16 + g;
                af[mt][0] = Asw[r * 20 + ks * 8 + t];
                af[mt][1] = Asw[(r + 8) * 20 + ks * 8 + t];
                af[mt][2] = Asw[r * 20 + ks * 8 + t + 4];
                af[mt][3] = Asw[(r + 8) * 20 + ks * 8 + t + 4];
            }
            uint32_t bf[4][2];
#pragma unroll
            for (int nt = 0; nt < 4; nt++) {
                const int c = wn + nt * 8 + g;
                bf[nt][0] = Bp[(ks * 8 + t) * 136 + c];
                bf[nt][1] = Bp[(ks * 8 + t + 4) * 136 + c];
            }
#pragma unroll
            for (int mt = 0; mt < 4; mt++)
#pragma unroll
                for (int nt = 0; nt < 4; nt++)
                    mma_f16(acc[mt][nt], af[mt], bf[nt]);
        }
        __syncthreads();
    }

    // ---- epilogue ----
#pragma unroll
    for (int mt = 0; mt < 4; mt++) {
#pragma unroll
        for (int nt = 0; nt < 4; nt++) {
            const int ccg = col0 + wn + nt * 8 + 2 * t;
            const float b0 = bias[ccg];
            const float b1 = bias[ccg + 1];
            const int r0 = row0 + wm + mt * 16 + g;
            if (QKV_SCATTER) {
                const int part = ccg >> 9;                 // 0=Q,1=K,2=V
                const int hh   = (ccg >> 6) & 7;
                const int d    = ccg & 63;
                __half* dst = (part == 0) ? g_Q : (part == 1) ? g_K : g_V;
                *(uint32_t*)&dst[((size_t)hh * NTOK + r0) * HD + d] =
                    pack2(acc[mt][nt][0] + b0, acc[mt][nt][1] + b1);
                *(uint32_t*)&dst[((size_t)hh * NTOK + r0 + 8) * HD + d] =
                    pack2(acc[mt][nt][2] + b0, acc[mt][nt][3] + b1);
            } else {
                float2 v0 = {acc[mt][nt][0] + b0, acc[mt][nt][1] + b1};
                float2 v1 = {acc[mt][nt][2] + b0, acc[mt][nt][3] + b1};
                *(float2*)&C[(size_t)r0 * NCOLS + ccg]       = v0;
                *(float2*)&C[(size_t)(r0 + 8) * NCOLS + ccg] = v1;
            }
        }
    }
}

// ---------------------------------------------------------------------------
// pe projection, log2-domain with static offset folded in.
// ---------------------------------------------------------------------------
__global__ void pe_proj(const float* __restrict__ pe,
                        const float* __restrict__ wpe,
                        const float* __restrict__ bpe) {
    const int n = blockIdx.x * 256 + threadIdx.x;
    if (n >= NTOK) return;
    float pv[DPE];
#pragma unroll
    for (int k = 0; k < DPE; k++) pv[k] = pe[n * DPE + k];
#pragma unroll
    for (int h = 0; h < NH; h++) {
        float s = bpe[h];
#pragma unroll
        for (int k = 0; k < DPE; k++) s += pv[k] * wpe[k * NH + h];
        g_peb[h * NTOK + n] = (s - SOFT_OFF) * LOG2E;
    }
}

// ---------------------------------------------------------------------------
// fp16 flash attention, static-offset softmax (round-15 structure).
// Only change: O written to g_AO as fp16 (out-proj consumes fp16 directly).
// ---------------------------------------------------------------------------
__global__ __launch_bounds__(256, 1) void attn_mma() {
    __shared__ __half Ks[64 * 72];     // [key][feat]
    __shared__ __half Vt[64 * 72];     // [feat][key]
    __shared__ float  pb[64];

    const int h    = blockIdx.y;
    const int tid  = threadIdx.x;
    const int warp = tid >> 5;
    const int lane = tid & 31;
    const int g    = lane >> 2;
    const int t    = lane & 3;
    const int qr0  = blockIdx.x * 256 + warp * 32;

    const __half* Qg = &g_Q[(size_t)h * NTOK * HD];
    const __half* Kg = &g_K[(size_t)h * NTOK * HD];
    const __half* Vg = &g_V[(size_t)h * NTOK * HD];
    const float*  pg = &g_peb[h * NTOK];

    const uint32_t* Ksw = (const uint32_t*)Ks;
    const uint32_t* Vtw = (const uint32_t*)Vt;

    uint32_t aq[2][4][4];
#pragma unroll
    for (int mt = 0; mt < 2; mt++) {
        const int r = qr0 + mt * 16 + g;
#pragma unroll
        for (int kk = 0; kk < 4; kk++) {
            aq[mt][kk][0] = *(const uint32_t*)&Qg[(size_t)r * HD + kk * 16 + 2 * t];
            aq[mt][kk][1] = *(const uint32_t*)&Qg[(size_t)(r + 8) * HD + kk * 16 + 2 * t];
            aq[mt][kk][2] = *(const uint32_t*)&Qg[(size_t)r * HD + kk * 16 + 2 * t + 8];
            aq[mt][kk][3] = *(const uint32_t*)&Qg[(size_t)(r + 8) * HD + kk * 16 + 2 * t + 8];
        }
    }

    float oacc[2][8][4];
#pragma unroll
    for (int mt = 0; mt < 2; mt++)
#pragma unroll
        for (int nt = 0; nt < 8; nt++)
#pragma unroll
            for (int c = 0; c < 4; c++) oacc[mt][nt][c] = 0.f;
    float lacc[2][4] = {{0.f, 0.f, 0.f, 0.f}, {0.f, 0.f, 0.f, 0.f}};

    uint32_t bones[2];
    bones[0] = bones[1] = (g == 0) ? 0x3C003C00u : 0u;

    const int krow0 = tid >> 3;
    const int kc8   = (tid & 7) << 3;
    const int vkp   = lane;
    const int vf8   = warp;

    uint4 kpre[2], vpa, vpb;
    float pbpre = 0.f;
    kpre[0] = *(const uint4*)&Kg[(size_t)krow0 * HD + kc8];
    kpre[1] = *(const uint4*)&Kg[(size_t)(krow0 + 32) * HD + kc8];
    vpa = *(const uint4*)&Vg[(size_t)(2 * vkp) * HD + vf8 * 8];
    vpb = *(const uint4*)&Vg[(size_t)(2 * vkp + 1) * HD + vf8 * 8];
    if (tid < 64) pbpre = pg[tid];

    for (int j0 = 0; j0 < NTOK; j0 += 64) {
        *(uint4*)&Ks[krow0 * 72 + kc8]        = kpre[0];
        *(uint4*)&Ks[(krow0 + 32) * 72 + kc8] = kpre[1];
        {
            const __half* ha = (const __half*)&vpa;
            const __half* hb = (const __half*)&vpb;
#pragma unroll
            for (int j = 0; j < 8; j++) {
                __half2 p = __halves2half2(ha[j], hb[j]);
                *(uint32_t*)&Vt[(vf8 * 8 + j) * 72 + 2 * vkp] =
                    *reinterpret_cast<uint32_t*>(&p);
            }
        }
        if (tid < 64) pb[tid] = pbpre;
        __syncthreads();

        {
            const int jn = (j0 + 64) & (NTOK - 1);
            kpre[0] = *(const uint4*)&Kg[(size_t)(jn + krow0) * HD + kc8];
            kpre[1] = *(const uint4*)&Kg[(size_t)(jn + krow0 + 32) * HD + kc8];
            vpa = *(const uint4*)&Vg[(size_t)(jn + 2 * vkp) * HD + vf8 * 8];
            vpb = *(const uint4*)&Vg[(size_t)(jn + 2 * vkp + 1) * HD + vf8 * 8];
            if (tid < 64) pbpre = pg[jn + tid];
        }

        float sacc[2][8][4];
#pragma unroll
        for (int mt = 0; mt < 2; mt++)
#pragma unroll
            for (int nt = 0; nt < 8; nt++)
#pragma unroll
                for (int c = 0; c < 4; c++) sacc[mt][nt][c] = 0.f;
#pragma unroll
        for (int kk = 0; kk < 4; kk++) {
#pragma unroll
            for (int nt = 0; nt < 8; nt++) {
                const int key = nt * 8 + g;
                uint32_t bf[2];
                bf[0] = Ksw[key * 36 + kk * 8 + t];
                bf[1] = Ksw[key * 36 + kk * 8 + t + 4];
                mma_f16(sacc[0][nt], aq[0][kk], bf);
                mma_f16(sacc[1][nt], aq[1][kk], bf);
            }
        }

#pragma unroll
        for (int mt = 0; mt < 2; mt++) {
            uint32_t pa[4][4];
#pragma unroll
            for (int kv = 0; kv < 4; kv++) {
                const int c0a = (2 * kv) * 8 + 2 * t;
                const int c0b = (2 * kv + 1) * 8 + 2 * t;
                const float pb0a = pb[c0a], pb1a = pb[c0a + 1];
                const float pb0b = pb[c0b], pb1b = pb[c0b + 1];
                pa[kv][0] = ex2_h2(pack2(fmaf(sacc[mt][2 * kv][0], SCALE2, pb0a),
                                         fmaf(sacc[mt][2 * kv][1], SCALE2, pb1a)));
                pa[kv][1] = ex2_h2(pack2(fmaf(sacc[mt][2 * kv][2], SCALE2, pb0a),
                                         fmaf(sacc[mt][2 * kv][3], SCALE2, pb1a)));
                pa[kv][2] = ex2_h2(pack2(fmaf(sacc[mt][2 * kv + 1][0], SCALE2, pb0b),
                                         fmaf(sacc[mt][2 * kv + 1][1], SCALE2, pb1b)));
                pa[kv][3] = ex2_h2(pack2(fmaf(sacc[mt][2 * kv + 1][2], SCALE2, pb0b),
                                         fmaf(sacc[mt][2 * kv + 1][3], SCALE2, pb1b)));
                mma_f16(lacc[mt], pa[kv], bones);
            }
#pragma unroll
            for (int kv = 0; kv < 4; kv++) {
#pragma unroll
                for (int nt = 0; nt < 8; nt++) {
                    const int f = nt * 8 + g;
                    uint32_t bf[2];
                    bf[0] = Vtw[f * 36 + kv * 8 + t];
                    bf[1] = Vtw[f * 36 + kv * 8 + t + 4];
                    mma_f16(oacc[mt][nt], pa[kv], bf);
                }
            }
        }
        __syncthreads();
    }

    // ---- normalize + write fp16 O ----
#pragma unroll
    for (int mt = 0; mt < 2; mt++) {
        const float l0 = __shfl_sync(0xffffffffu, lacc[mt][0], lane & 0x1C);
        const float l1 = __shfl_sync(0xffffffffu, lacc[mt][2], lane & 0x1C);
        const float inv0 = 1.f / l0;
        const float inv1 = 1.f / l1;
        const int r = qr0 + mt * 16 + g;
#pragma unroll
        for (int nt = 0; nt < 8; nt++) {
            const int d = nt * 8 + 2 * t;
            *(uint32_t*)&g_AO[(size_t)r * DM + h * HD + d] =
                pack2(oacc[mt][nt][0] * inv0, oacc[mt][nt][1] * inv0);
            *(uint32_t*)&g_AO[(size_t)(r + 8) * DM + h * HD + d] =
                pack2(oacc[mt][nt][2] * inv1, oacc[mt][nt][3] * inv1);
        }
    }
}

// ---------------------------------------------------------------------------
extern "C" void kernel_launch(void* const* d_in, const int* in_sizes, int n_in,
                              void* d_out, int out_size) {
    const float* x     = (const float*)d_in[0];
    const float* pe    = (const float*)d_in[1];
    const float* w_qkv = (const float*)d_in[2];
    const float* b_qkv = (const float*)d_in[3];
    const float* w_pe  = (const float*)d_in[4];
    const float* b_pe  = (const float*)d_in[5];
    const float* w_out = (const float*)d_in[6];
    const float* b_out = (const float*)d_in[7];
    float* out = (float*)d_out;

    // fp32 -> fp16 pre-conversion of x, w_qkv, w_out
    cvt_inputs<<<(CVT_NX + CVT_NQ + CVT_NO) / 256, 256>>>(x, w_qkv, w_out);

    // pe projection (key-side softmax bias, log2-scaled, offset folded)
    pe_proj<<<NTOK / 256, 256>>>(pe, w_pe, b_pe);

    // QKV projection: 4096x1536, blocks 128x128 -> (32, 12), 2 CTAs/SM
    gemm_mma<3 * DM, true><<<dim3(32, 12), 256>>>(b_qkv, nullptr);

    // flash attention: 16 query blocks x 8 heads = 128 CTAs (single wave)
    attn_mma<<<dim3(16, NH), 256>>>();

    // output projection: 4096x512 -> (32, 4), 2 CTAs/SM
    gemm_mma<DM, false><<<dim3(32, 4), 256>>>(b_out, out);
}